// round 1
// baseline (speedup 1.0000x reference)
#include <cuda_runtime.h>

// Problem constants
#define B_  64
#define H_  128
#define W_  128
#define R_  4
#define GW_ 32
#define N_  1024   // GH*GW
#define D_  16
#define S_  32

// Scratch: extracted patch diagonals xd[b][n][r]  (1 MiB)
__device__ float g_xd[B_ * N_ * R_];

// Kernel 1: extract xd[b,n,r] = x[b, 0, (n/32)*4 + r, (n%32)*4 + r]
__global__ void __launch_bounds__(256) extract_xd_kernel(const float* __restrict__ x) {
    int tid = blockIdx.x * blockDim.x + threadIdx.x;   // over B*N = 65536
    if (tid >= B_ * N_) return;
    int b = tid >> 10;
    int n = tid & (N_ - 1);
    int i = n >> 5;
    int j = n & (GW_ - 1);
    const float* xb = x + (size_t)b * (H_ * W_) + i * (R_ * W_) + j * R_;
    float4 v;
    v.x = xb[0 * W_ + 0];
    v.y = xb[1 * W_ + 1];
    v.z = xb[2 * W_ + 2];
    v.w = xb[3 * W_ + 3];
    reinterpret_cast<float4*>(g_xd)[tid] = v;          // coalesced 16B/thread
}

// Kernel 2: out[b,n,d,s] = sum_r xd[b,n,r] * pesos[n,d,s,r,r]
// One warp handles (n, d_base..d_base+3). Lane = (d_off = lane>>3, s-quad = (lane&7)*4).
// Weights live in registers for the whole b-loop (64x reuse).
__global__ void __launch_bounds__(256) conexao_main_kernel(
    const float* __restrict__ pesos, float* __restrict__ out) {

    int warp = (blockIdx.x * blockDim.x + threadIdx.x) >> 5;  // 0..4095 = N*D/4
    int lane = threadIdx.x & 31;

    int n  = warp >> 2;                          // 0..1023
    int d  = ((warp & 3) << 2) + (lane >> 3);    // 0..15
    int s4 = (lane & 7) << 2;                    // s base of this lane's quad

    // Load 16 diagonal weights: pesos[((n*D+d)*S + s)*16 + r*5]
    const float* wbase = pesos + ((size_t)(n * D_ + d) * S_ + s4) * (R_ * R_);
    float w[4][4];
    #pragma unroll
    for (int ss = 0; ss < 4; ss++)
        #pragma unroll
        for (int r = 0; r < 4; r++)
            w[ss][r] = wbase[ss * (R_ * R_) + r * (R_ + 1)];

    const float4* xd = reinterpret_cast<const float4*>(g_xd) + n;       // stride N_ per b
    float4* o = reinterpret_cast<float4*>(out)
              + ((size_t)(n * D_ + d) * S_ + s4) / 4;                   // stride N*D*S/4 per b

    const int xd_stride = N_;
    const int o_stride  = (N_ * D_ * S_) / 4;

    #pragma unroll 4
    for (int b = 0; b < B_; b++) {
        float4 xv = xd[(size_t)b * xd_stride];   // uniform per warp -> broadcast
        float4 ov;
        ov.x = xv.x * w[0][0] + xv.y * w[0][1] + xv.z * w[0][2] + xv.w * w[0][3];
        ov.y = xv.x * w[1][0] + xv.y * w[1][1] + xv.z * w[1][2] + xv.w * w[1][3];
        ov.z = xv.x * w[2][0] + xv.y * w[2][1] + xv.z * w[2][2] + xv.w * w[2][3];
        ov.w = xv.x * w[3][0] + xv.y * w[3][1] + xv.z * w[3][2] + xv.w * w[3][3];
        o[(size_t)b * o_stride] = ov;            // warp stores 2KB contiguous
    }
}

extern "C" void kernel_launch(void* const* d_in, const int* in_sizes, int n_in,
                              void* d_out, int out_size) {
    const float* x     = (const float*)d_in[0];   // [64,1,128,128]
    const float* pesos = (const float*)d_in[1];   // [1024,16,32,4,4]
    float* out = (float*)d_out;                   // [64,1024,16,32]

    // Kernel 1: 65536 threads
    extract_xd_kernel<<<(B_ * N_) / 256, 256>>>(x);

    // Kernel 2: N*D/4 warps = 4096 warps = 131072 threads = 512 blocks
    conexao_main_kernel<<<(N_ * D_ / 4 * 32) / 256, 256>>>(pesos, out);
}